// round 17
// baseline (speedup 1.0000x reference)
#include <cuda_runtime.h>

typedef unsigned long long ull;

// ---- Blackwell packed fp32x2 math (one instruction = two fp32 lanes) ----
#define F2FMA(d,a,b,c) asm("fma.rn.f32x2 %0, %1, %2, %3;" : "=l"(d) : "l"(a), "l"(b), "l"(c))

__device__ __forceinline__ ull pk(float lo, float hi) {
    ull r; asm("mov.b64 %0, {%1, %2};" : "=l"(r) : "f"(lo), "f"(hi)); return r;
}
__device__ __forceinline__ void upk(ull v, float& lo, float& hi) {
    asm("mov.b64 {%0, %1}, %2;" : "=f"(lo), "=f"(hi) : "l"(v));
}

// HW tanh (MUFU, sm_75+): abs err ~6e-4; random-sign accumulation across the
// 768-term weighted dot keeps the score error ~4e-4 RMS -> well under 1e-3.
__device__ __forceinline__ float tanh_hw(float x) {
    float y; asm("tanh.approx.f32 %0, %1;" : "=f"(y) : "f"(x)); return y;
}

constexpr int Bc = 16, Tc = 4096, Ec = 768;
constexpr int SPLITS = 46;          // 46*16 = 736 CTAs ~ one wave @ 5 CTAs/SM (740 slots)
constexpr int RPC    = 90;          // ceil(4096/46); last split covers 46
constexpr int PCH    = 23;          // rows per warp-PAIR (4*23=92 >= 90; fits 32-bit mask)
constexpr int NPAIR  = 4;           // 8 warps = 4 pairs
constexpr int NP     = 6;           // fp32x2 pairs per lane (12 floats = 384/32)
constexpr int HE     = Ec / 2;      // 384: e-columns per half-warp

// plain-sum split partials (no log-sum-exp needed: scores bounded, max fixed at 0)
__device__ float g_pacc[Bc * SPLITS * Ec];
__device__ float g_pl [Bc * SPLITS];
__device__ int   g_cnt [Bc];        // zero-init; self-resetting (last CTA clears)

// score of two half-rows (all 6 LDG.128 issued up front; HW tanh + scalar dot)
__device__ __forceinline__ void score2(const float4* __restrict__ rowA,
                                       const float4* __restrict__ rowB,
                                       const float* __restrict__ wl, int lane,
                                       float& sA, float& sB)
{
    float4 fa0 = rowA[lane], fa1 = rowA[lane + 32], fa2 = rowA[lane + 64];
    float4 fb0 = rowB[lane], fb1 = rowB[lane + 32], fb2 = rowB[lane + 64];
    float a = 0.f, b = 0.f;
    a = fmaf(tanh_hw(fa0.x), wl[0],   a);  b = fmaf(tanh_hw(fb0.x), wl[0],   b);
    a = fmaf(tanh_hw(fa0.y), wl[1],   a);  b = fmaf(tanh_hw(fb0.y), wl[1],   b);
    a = fmaf(tanh_hw(fa0.z), wl[2],   a);  b = fmaf(tanh_hw(fb0.z), wl[2],   b);
    a = fmaf(tanh_hw(fa0.w), wl[3],   a);  b = fmaf(tanh_hw(fb0.w), wl[3],   b);
    a = fmaf(tanh_hw(fa1.x), wl[128], a);  b = fmaf(tanh_hw(fb1.x), wl[128], b);
    a = fmaf(tanh_hw(fa1.y), wl[129], a);  b = fmaf(tanh_hw(fb1.y), wl[129], b);
    a = fmaf(tanh_hw(fa1.z), wl[130], a);  b = fmaf(tanh_hw(fb1.z), wl[130], b);
    a = fmaf(tanh_hw(fa1.w), wl[131], a);  b = fmaf(tanh_hw(fb1.w), wl[131], b);
    a = fmaf(tanh_hw(fa2.x), wl[256], a);  b = fmaf(tanh_hw(fb2.x), wl[256], b);
    a = fmaf(tanh_hw(fa2.y), wl[257], a);  b = fmaf(tanh_hw(fb2.y), wl[257], b);
    a = fmaf(tanh_hw(fa2.z), wl[258], a);  b = fmaf(tanh_hw(fb2.z), wl[258], b);
    a = fmaf(tanh_hw(fa2.w), wl[259], a);  b = fmaf(tanh_hw(fb2.w), wl[259], b);
    #pragma unroll
    for (int o = 16; o; o >>= 1) {          // two independent butterfly trees
        a += __shfl_xor_sync(0xffffffffu, a, o);
        b += __shfl_xor_sync(0xffffffffu, b, o);
    }
    sA = a; sB = b;
}

// weighted accumulate of two half-rows (L1/L2-hot: just read in score phase)
__device__ __forceinline__ void accum2(const float4* __restrict__ rowA,
                                       const float4* __restrict__ rowB,
                                       float pwA, float pwB, int lane, ull acc[NP])
{
    float4 fa0 = rowA[lane], fa1 = rowA[lane + 32], fa2 = rowA[lane + 64];
    float4 fb0 = rowB[lane], fb1 = rowB[lane + 32], fb2 = rowB[lane + 64];
    const ull pA = pk(pwA, pwA), pB = pk(pwB, pwB);
    F2FMA(acc[0], pk(fa0.x, fa0.y), pA, acc[0]);
    F2FMA(acc[1], pk(fa0.z, fa0.w), pA, acc[1]);
    F2FMA(acc[2], pk(fa1.x, fa1.y), pA, acc[2]);
    F2FMA(acc[3], pk(fa1.z, fa1.w), pA, acc[3]);
    F2FMA(acc[4], pk(fa2.x, fa2.y), pA, acc[4]);
    F2FMA(acc[5], pk(fa2.z, fa2.w), pA, acc[5]);
    F2FMA(acc[0], pk(fb0.x, fb0.y), pB, acc[0]);
    F2FMA(acc[1], pk(fb0.z, fb0.w), pB, acc[1]);
    F2FMA(acc[2], pk(fb1.x, fb1.y), pB, acc[2]);
    F2FMA(acc[3], pk(fb1.z, fb1.w), pB, acc[3]);
    F2FMA(acc[4], pk(fb2.x, fb2.y), pB, acc[4]);
    F2FMA(acc[5], pk(fb2.z, fb2.w), pB, acc[5]);
}

__global__ void __launch_bounds__(256, 5)
attn_pass1(const float* __restrict__ ctx, const int* __restrict__ mask,
           const float* __restrict__ vw, float* __restrict__ out)
{
    const int b = blockIdx.y, split = blockIdx.x;
    const int tid = threadIdx.x, wid = tid >> 5, lane = tid & 31;
    const int pair = wid >> 1, half = wid & 1;

    __shared__ float s_acc[NPAIR][Ec];      // 12 KB
    __shared__ float s_w2[Ec];              // 3 KB: second half of v_w
    __shared__ float s_half[NPAIR][2][32];  // 1 KB: per-row half-scores
    __shared__ float s_l[NPAIR];
    __shared__ int   s_last;

    if (tid < Ec / 4)
        reinterpret_cast<float4*>(s_w2)[tid] =
            reinterpret_cast<const float4*>(vw + Ec)[tid];
    if (tid < NPAIR) s_l[tid] = 0.f;        // pairs with no rows never write s_l

    // this PAIR's contiguous row range inside the split (both warps identical)
    const int r0  = split * RPC;
    const int r1  = min(r0 + RPC, Tc);
    const int pr0 = r0 + pair * PCH;
    const int cnt = min(PCH, r1 - pr0);     // may be <= 0 on tail pairs

    // pre-ballot mask bits: identical in both warps of the pair -> identical
    // control flow -> the per-tile named barrier below is always matched
    const int* mrow = mask + b * Tc + pr0;
    int mv = (lane < cnt) ? mrow[lane] : 0;
    const unsigned mb = __ballot_sync(0xffffffffu, mv != 0);

    // this warp reads its half of each row: 3 float4 per lane, coalesced
    const float4* cb = reinterpret_cast<const float4*>(ctx)
                     + ((size_t)b * Tc + (size_t)pr0) * (Ec / 4) + half * (HE / 4);

    __syncthreads();                        // s_w2 + s_l ready

    const float* wl = s_w2 + half * HE + 4 * lane;
    const int barid = pair + 1;             // named barriers 1..4, 64 threads each

    float lsum = 0.f;                       // identical in all 64 pair threads
    ull acc[NP];
    #pragma unroll
    for (int p = 0; p < NP; p++) acc[p] = 0ULL;

    // ---- tiled two-phase: 4 rows scored, 1 barrier, 4 rows accumulated ----
    // (slots in s_half differ across tiles -> no WAR race, 1 barrier/tile)
    unsigned m = mb;
    while (m) {
        int rows[4]; int nr = 0;
        #pragma unroll
        for (int i = 0; i < 4; i++) {
            if (m) { rows[i] = __ffs(m) - 1; m &= m - 1; nr++; }
            else     rows[i] = rows[0];     // duplicate tail; weight forced to 0
        }
        const float4* rp0 = cb + (size_t)rows[0] * (Ec / 4);
        const float4* rp1 = cb + (size_t)rows[1] * (Ec / 4);
        const float4* rp2 = cb + (size_t)rows[2] * (Ec / 4);
        const float4* rp3 = cb + (size_t)rows[3] * (Ec / 4);

        float s0, s1, s2, s3;
        score2(rp0, rp1, wl, lane, s0, s1);
        if (nr > 2) score2(rp2, rp3, wl, lane, s2, s3);
        if (lane == 0) {
            s_half[pair][half][rows[0]] = s0;
            if (nr > 1) s_half[pair][half][rows[1]] = s1;
            if (nr > 2) s_half[pair][half][rows[2]] = s2;
            if (nr > 3) s_half[pair][half][rows[3]] = s3;
        }
        asm volatile("bar.sync %0, %1;" :: "r"(barid), "r"(64) : "memory");

        // both warps recompute identical exps from smem (no shuffle, no 2nd bar)
        float pw0 = __expf(s_half[pair][0][rows[0]] + s_half[pair][1][rows[0]]);
        float pw1 = (nr > 1) ? __expf(s_half[pair][0][rows[1]] + s_half[pair][1][rows[1]]) : 0.f;
        lsum += pw0 + pw1;
        accum2(rp0, rp1, pw0, pw1, lane, acc);
        if (nr > 2) {
            float pw2 = __expf(s_half[pair][0][rows[2]] + s_half[pair][1][rows[2]]);
            float pw3 = (nr > 3) ? __expf(s_half[pair][0][rows[3]] + s_half[pair][1][rows[3]]) : 0.f;
            lsum += pw2 + pw3;
            accum2(rp2, rp3, pw2, pw3, lane, acc);
        }
    }

    // ---- CTA combine: each pair wrote a full Ec; sum the 4 pairs ----
    if (lane == 0 && half == 0 && mb) s_l[pair] = lsum;
    float4* sa = reinterpret_cast<float4*>(&s_acc[pair][half * HE]);
    #pragma unroll
    for (int k = 0; k < 3; k++) {
        float a0, a1, b0, b1;
        upk(acc[2*k],   a0, a1);
        upk(acc[2*k+1], b0, b1);
        sa[lane + 32 * k] = make_float4(a0, a1, b0, b1);
    }
    __syncthreads();

    const int cta = b * SPLITS + split;
    if (tid < Ec / 4) {
        float4 v = make_float4(0.f, 0.f, 0.f, 0.f);
        #pragma unroll
        for (int p = 0; p < NPAIR; p++) {
            float4 t = reinterpret_cast<const float4*>(s_acc[p])[tid];
            v.x += t.x; v.y += t.y; v.z += t.z; v.w += t.w;
        }
        reinterpret_cast<float4*>(g_pacc)[cta * (Ec / 4) + tid] = v;
    }
    if (tid == 0) {
        float L = 0.f;
        #pragma unroll
        for (int p = 0; p < NPAIR; p++) L += s_l[p];
        g_pl[cta] = L;
    }

    // ---- last CTA of this batch performs the combine + normalize ----
    __threadfence();                        // make this CTA's partials globally visible
    __syncthreads();                        // all threads' stores issued before the atomic
    if (tid == 0) {
        int old = atomicAdd(&g_cnt[b], 1);
        s_last = (old == SPLITS - 1) ? 1 : 0;
    }
    __syncthreads();
    if (!s_last) return;

    float L = 0.f;
    #pragma unroll
    for (int s = 0; s < SPLITS; s++) L += g_pl[b * SPLITS + s];
    const float invL = 1.0f / L;

    if (tid < Ec / 4) {
        float4 v = make_float4(0.f, 0.f, 0.f, 0.f);
        #pragma unroll
        for (int s = 0; s < SPLITS; s++) {  // 46 independent L2-hot float4 loads
            float4 t = reinterpret_cast<const float4*>(g_pacc)[(b * SPLITS + s) * (Ec / 4) + tid];
            v.x += t.x; v.y += t.y; v.z += t.z; v.w += t.w;
        }
        v.x *= invL; v.y *= invL; v.z *= invL; v.w *= invL;
        reinterpret_cast<float4*>(out)[b * (Ec / 4) + tid] = v;
    }
    if (tid == 0) g_cnt[b] = 0;             // self-reset for the next graph replay
}

extern "C" void kernel_launch(void* const* d_in, const int* in_sizes, int n_in,
                              void* d_out, int out_size)
{
    // metadata order: query [16,768] (unused: softmax-invariant), context [16,4096,768],
    //                 mask [16,4096] int32, v_w [1536]
    const float* ctx  = (const float*)d_in[1];
    const int*   mask = (const int*)  d_in[2];
    const float* vw   = (const float*)d_in[3];
    float*       out  = (float*)d_out;

    attn_pass1<<<dim3(SPLITS, Bc), 256>>>(ctx, mask, vw, out);
}